// round 1
// baseline (speedup 1.0000x reference)
#include <cuda_runtime.h>
#include <math.h>

#define BB 32
#define NN 1024
#define IND 64
#define ATTN 128
#define OUTD 64
#define CTOT 320   // Q(128) | K(128) | V(64)

// ---------------- scratch (device globals; no allocations allowed) ----------
__device__ float g_deg[BB * NN];
__device__ float g_diag[BB * NN];
__device__ float g_H[(size_t)BB * NN * CTOT];   // d_k-prescaled x@W, 40 MB
__device__ float g_Q[(size_t)BB * NN * ATTN];   // 16 MB
__device__ float g_K[(size_t)BB * NN * ATTN];   // 16 MB

// ---------------- kernel A: row degrees + diagonal -------------------------
__global__ void __launch_bounds__(256) deg_kernel(const float* __restrict__ adj) {
    int warp = (blockIdx.x * blockDim.x + threadIdx.x) >> 5;
    int lane = threadIdx.x & 31;
    if (warp >= BB * NN) return;
    const float* row = adj + (size_t)warp * NN;
    const float4* r4 = (const float4*)row;
    float s = 0.f;
#pragma unroll
    for (int j = lane; j < NN / 4; j += 32) {
        float4 v = r4[j];
        s += (v.x + v.y) + (v.z + v.w);
    }
#pragma unroll
    for (int o = 16; o; o >>= 1) s += __shfl_xor_sync(0xffffffffu, s, o);
    if (lane == 0) {
        int i = warp & (NN - 1);
        float dg = row[i];
        float rs = s - dg + 1.0f;          // replace diag by 1
        g_deg[warp]  = rsqrtf(fmaxf(rs, 1.0f));
        g_diag[warp] = dg;
    }
}

// ---------------- kernel B: H' = diag(d) * (x @ [Wq|Wk|Wv]) -----------------
__global__ void __launch_bounds__(320) h_kernel(const float* __restrict__ x,
                                                const float* __restrict__ Wq,
                                                const float* __restrict__ Wk,
                                                const float* __restrict__ Wv) {
    __shared__ float xs[64][IND];  // 16 KB
    int b = blockIdx.y;
    int rb = blockIdx.x;           // 16 row blocks of 64
    int t = threadIdx.x;           // 0..319 == output column
    size_t rowbase = ((size_t)b * NN + rb * 64);

    for (int idx = t; idx < 64 * IND; idx += 320) {
        int r = idx >> 6, k = idx & 63;
        xs[r][k] = x[(rowbase + r) * IND + k];
    }
    __syncthreads();

    const float* Wcol;
    int stride;
    if (t < 128)      { Wcol = Wq + t;          stride = 128; }
    else if (t < 256) { Wcol = Wk + (t - 128);  stride = 128; }
    else              { Wcol = Wv + (t - 256);  stride = 64;  }

    float w[64];
#pragma unroll
    for (int k = 0; k < 64; k++) w[k] = Wcol[(size_t)k * stride];

    const float4* xs4 = (const float4*)&xs[0][0];
    for (int r = 0; r < 64; r++) {
        float acc = 0.f;
#pragma unroll
        for (int kq = 0; kq < 16; kq++) {
            float4 xv = xs4[r * 16 + kq];
            acc += xv.x * w[kq * 4 + 0];
            acc += xv.y * w[kq * 4 + 1];
            acc += xv.z * w[kq * 4 + 2];
            acc += xv.w * w[kq * 4 + 3];
        }
        g_H[(rowbase + r) * CTOT + t] = g_deg[rowbase + r] * acc;
    }
}

// ---------------- kernel C: C = diag(d) * adjD * H' + bias  -----------------
// adjD = adj with diag=1, handled as raw-adj GEMM + (1-diag_i)*H'[i,:] correction.
#define MT 256
#define KT 32
#define NT 64

__global__ void __launch_bounds__(256, 2) gcn_gemm_kernel(const float* __restrict__ adj,
                                                          const float* __restrict__ bq,
                                                          const float* __restrict__ bk,
                                                          const float* __restrict__ bv,
                                                          float* __restrict__ outV) {
    __shared__ float As[KT][MT + 4];  // transposed adj tile, 33280 B
    __shared__ float Bs[KT][NT + 4];  // H' tile, 8704 B

    int b  = blockIdx.z;
    int mt = blockIdx.y;   // 0..3 (256-row tiles)
    int cb = blockIdx.x;   // 0..4 (64-col tiles of the 320 output cols)
    int t  = threadIdx.x;
    int ty = t >> 3;       // 0..31 -> 8 rows each
    int tx = t & 7;        // 0..7  -> 8 cols each

    const float* adjb = adj + (size_t)b * NN * NN;
    const float* Hb   = g_H + (size_t)b * NN * CTOT;

    float acc[8][8];
#pragma unroll
    for (int r = 0; r < 8; r++)
#pragma unroll
        for (int c = 0; c < 8; c++) acc[r][c] = 0.f;

    for (int k0 = 0; k0 < NN; k0 += KT) {
        // load adj tile [256 rows x 32 k], store transposed
#pragma unroll
        for (int i = 0; i < 8; i++) {
            int idx = t + i * 256;       // 0..2047
            int r = idx >> 3, q = idx & 7;
            float4 v = *(const float4*)(adjb + (size_t)(mt * MT + r) * NN + k0 + q * 4);
            As[q * 4 + 0][r] = v.x;
            As[q * 4 + 1][r] = v.y;
            As[q * 4 + 2][r] = v.z;
            As[q * 4 + 3][r] = v.w;
        }
        // load H' tile [32 k x 64 cols]
#pragma unroll
        for (int i = 0; i < 2; i++) {
            int idx = t + i * 256;       // 0..511
            int kk = idx >> 4, q = idx & 15;
            float4 v = *(const float4*)(Hb + (size_t)(k0 + kk) * CTOT + cb * NT + q * 4);
            *(float4*)&Bs[kk][q * 4] = v;
        }
        __syncthreads();

#pragma unroll
        for (int kk = 0; kk < KT; kk++) {
            float a[8], bb[8];
            *(float4*)&a[0]  = *(const float4*)&As[kk][ty * 8];
            *(float4*)&a[4]  = *(const float4*)&As[kk][ty * 8 + 4];
            *(float4*)&bb[0] = *(const float4*)&Bs[kk][tx * 8];
            *(float4*)&bb[4] = *(const float4*)&Bs[kk][tx * 8 + 4];
#pragma unroll
            for (int r = 0; r < 8; r++)
#pragma unroll
                for (int c = 0; c < 8; c++) acc[r][c] += a[r] * bb[c];
        }
        __syncthreads();
    }

    // epilogue
    int jbase = cb * NT + tx * 8;
    float bias[8];
#pragma unroll
    for (int jj = 0; jj < 8; jj++) {
        int j = jbase + jj;
        bias[jj] = (j < 128) ? bq[j] : (j < 256 ? bk[j - 128] : bv[j - 256]);
    }
#pragma unroll
    for (int r = 0; r < 8; r++) {
        int i = mt * MT + ty * 8 + r;
        size_t gi = (size_t)b * NN + i;
        float d    = g_deg[gi];
        float corr = 1.0f - g_diag[gi];
#pragma unroll
        for (int jj = 0; jj < 8; jj++) {
            int j = jbase + jj;
            float v = d * (acc[r][jj] + corr * Hb[(size_t)i * CTOT + j]) + bias[jj];
            if (j < 128)      g_Q[gi * ATTN + j] = v;
            else if (j < 256) g_K[gi * ATTN + (j - 128)] = v;
            else              outV[gi * OUTD + (j - 256)] = v;
        }
    }
}

// ---------------- kernel D: A = sym(mean_h tanh(Qh Khᵀ / 8)) ----------------
// Tile-pair scheme: block (I,J), I<=J computes raw tiles (I,J) and (J,I),
// symmetrizes in-block, writes both output tiles. No separate symmetrize pass.
#define QROW 132                 // padded Q/K tile row (floats)
#define TROW 65                  // padded 64x64 tile row

__device__ __forceinline__ void load_tile64(float* dst, const float* src,
                                            int b, int tile, int t) {
    const float* p = src + ((size_t)b * NN + tile * 64) * ATTN;
    for (int idx = t; idx < 64 * 32; idx += 256) {   // float4 units
        int r = idx >> 5, q = idx & 31;
        float4 v = *(const float4*)(p + r * ATTN + q * 4);
        *(float4*)(dst + r * QROW + q * 4) = v;
    }
}

__device__ __forceinline__ void compute_tile(const float* Qs, const float* Ks,
                                             int i0, int j0, float out[4][4]) {
#pragma unroll
    for (int r = 0; r < 4; r++)
#pragma unroll
        for (int s = 0; s < 4; s++) out[r][s] = 0.f;
#pragma unroll
    for (int h = 0; h < 4; h++) {
        float acc[4][4];
#pragma unroll
        for (int r = 0; r < 4; r++)
#pragma unroll
            for (int s = 0; s < 4; s++) acc[r][s] = 0.f;
#pragma unroll
        for (int cq = h * 8; cq < h * 8 + 8; cq++) {
            float4 qa[4], kb[4];
#pragma unroll
            for (int r = 0; r < 4; r++)
                qa[r] = *(const float4*)(Qs + (i0 + r) * QROW + cq * 4);
#pragma unroll
            for (int s = 0; s < 4; s++)
                kb[s] = *(const float4*)(Ks + (j0 + s) * QROW + cq * 4);
#pragma unroll
            for (int r = 0; r < 4; r++)
#pragma unroll
                for (int s = 0; s < 4; s++) {
                    acc[r][s] += qa[r].x * kb[s].x;
                    acc[r][s] += qa[r].y * kb[s].y;
                    acc[r][s] += qa[r].z * kb[s].z;
                    acc[r][s] += qa[r].w * kb[s].w;
                }
        }
#pragma unroll
        for (int r = 0; r < 4; r++)
#pragma unroll
            for (int s = 0; s < 4; s++)
                out[r][s] += tanhf(acc[r][s] * 0.125f);   // / sqrt(OUT_DIM)=8
    }
#pragma unroll
    for (int r = 0; r < 4; r++)
#pragma unroll
        for (int s = 0; s < 4; s++) out[r][s] *= 0.25f;   // head mean
}

#define SMEM_D ((2 * 64 * QROW + 2 * 64 * TROW) * (int)sizeof(float))  // 100864 B

__global__ void __launch_bounds__(256) attn_kernel(float* __restrict__ outA) {
    extern __shared__ float sm[];
    float* Qs = sm;
    float* Ks = sm + 64 * QROW;
    float* T1 = sm + 2 * 64 * QROW;
    float* C2 = T1 + 64 * TROW;

    int I = blockIdx.x, J = blockIdx.y, b = blockIdx.z;
    if (J < I) return;
    int t = threadIdx.x;
    int i0 = (t & 15) * 4;     // local row group
    int j0 = (t >> 4) * 4;     // local col group

    load_tile64(Qs, g_Q, b, I, t);
    load_tile64(Ks, g_K, b, J, t);
    __syncthreads();

    float t1[4][4];
    compute_tile(Qs, Ks, i0, j0, t1);   // raw tile (I,J)
#pragma unroll
    for (int r = 0; r < 4; r++)
#pragma unroll
        for (int s = 0; s < 4; s++) T1[(i0 + r) * TROW + (j0 + s)] = t1[r][s];
    __syncthreads();   // T1 complete, Qs/Ks free

    if (I == J) {
#pragma unroll
        for (int r = 0; r < 4; r++)
#pragma unroll
            for (int s = 0; s < 4; s++)
                C2[(i0 + r) * TROW + (j0 + s)] =
                    0.5f * (T1[(i0 + r) * TROW + (j0 + s)] +
                            T1[(j0 + s) * TROW + (i0 + r)]);
        __syncthreads();
    } else {
        load_tile64(Qs, g_Q, b, J, t);
        load_tile64(Ks, g_K, b, I, t);
        __syncthreads();
        float t2[4][4];
        compute_tile(Qs, Ks, i0, j0, t2);  // raw tile (J,I): rows in J, cols in I
        // A[J*64+i0+r][I*64+j0+s] = 0.5*(raw(J,I) + raw(I,J)^T)
#pragma unroll
        for (int r = 0; r < 4; r++)
#pragma unroll
            for (int s = 0; s < 4; s++)
                C2[(i0 + r) * TROW + (j0 + s)] =
                    0.5f * (t2[r][s] + T1[(j0 + s) * TROW + (i0 + r)]);
        __syncthreads();
    }

    // C2 holds output tile (J,I); write it, and its transpose to (I,J).
    float* ob = outA + ((size_t)b * NN + J * 64) * NN + I * 64;
    for (int idx = t; idx < 4096; idx += 256) {
        int r = idx >> 6, c = idx & 63;
        ob[(size_t)r * NN + c] = C2[r * TROW + c];
    }
    if (I != J) {
        float* ob2 = outA + ((size_t)b * NN + I * 64) * NN + J * 64;
        for (int idx = t; idx < 4096; idx += 256) {
            int r = idx >> 6, c = idx & 63;
            ob2[(size_t)r * NN + c] = C2[c * TROW + r];
        }
    }
}

// ---------------- launch -----------------------------------------------------
extern "C" void kernel_launch(void* const* d_in, const int* in_sizes, int n_in,
                              void* d_out, int out_size) {
    (void)in_sizes; (void)n_in; (void)out_size;
    const float* x   = (const float*)d_in[0];
    const float* adj = (const float*)d_in[1];
    // d_in[2] = flags (unused by reference)
    const float* Wq = (const float*)d_in[3];
    const float* bq = (const float*)d_in[4];
    const float* Wk = (const float*)d_in[5];
    const float* bk = (const float*)d_in[6];
    const float* Wv = (const float*)d_in[7];
    const float* bv = (const float*)d_in[8];

    float* outV = (float*)d_out;                            // [B,N,64]
    float* outA = (float*)d_out + (size_t)BB * NN * OUTD;   // [B,N,N]

    cudaFuncSetAttribute(attn_kernel,
                         cudaFuncAttributeMaxDynamicSharedMemorySize, SMEM_D);

    deg_kernel<<<(BB * NN) / 8, 256>>>(adj);
    h_kernel<<<dim3(16, BB), 320>>>(x, Wq, Wk, Wv);
    gcn_gemm_kernel<<<dim3(5, 4, BB), 256>>>(adj, bq, bk, bv, outV);
    attn_kernel<<<dim3(16, 16, BB), 256, SMEM_D>>>(outA);
}

// round 2
// speedup vs baseline: 2.3988x; 2.3988x over previous
#include <cuda_runtime.h>
#include <math.h>
#include <cstdint>

#define BB 32
#define NN 1024
#define IND 64
#define ATTN 128
#define OUTD 64
#define CTOT 320   // Q(128) | K(128) | V(64)

// ---------------- scratch (device globals; no allocations allowed) ----------
__device__ float g_deg[BB * NN];
__device__ float g_diag[BB * NN];
__device__ float g_H[(size_t)BB * NN * CTOT];   // d-prescaled x@W, 40 MB
__device__ float g_Q[(size_t)BB * NN * ATTN];   // 16 MB
__device__ float g_K[(size_t)BB * NN * ATTN];   // 16 MB

// ---------------- tf32 MMA helpers -----------------------------------------
__device__ __forceinline__ uint32_t f2tf32(float x) {
    uint32_t r;
    asm("cvt.rna.tf32.f32 %0, %1;" : "=r"(r) : "f"(x));
    return r;
}

__device__ __forceinline__ void mma_tf32(float c[4],
                                         uint32_t a0, uint32_t a1, uint32_t a2, uint32_t a3,
                                         uint32_t b0, uint32_t b1) {
    asm volatile(
        "mma.sync.aligned.m16n8k8.row.col.f32.tf32.tf32.f32 "
        "{%0,%1,%2,%3}, {%4,%5,%6,%7}, {%8,%9}, {%0,%1,%2,%3};\n"
        : "+f"(c[0]), "+f"(c[1]), "+f"(c[2]), "+f"(c[3])
        : "r"(a0), "r"(a1), "r"(a2), "r"(a3), "r"(b0), "r"(b1));
}

// ---------------- kernel A: row degrees + diagonal --------------------------
__global__ void __launch_bounds__(256) deg_kernel(const float* __restrict__ adj) {
    int warp = (blockIdx.x * blockDim.x + threadIdx.x) >> 5;
    int lane = threadIdx.x & 31;
    if (warp >= BB * NN) return;
    const float* row = adj + (size_t)warp * NN;
    const float4* r4 = (const float4*)row;
    float s = 0.f;
#pragma unroll
    for (int j = lane; j < NN / 4; j += 32) {
        float4 v = r4[j];
        s += (v.x + v.y) + (v.z + v.w);
    }
#pragma unroll
    for (int o = 16; o; o >>= 1) s += __shfl_xor_sync(0xffffffffu, s, o);
    if (lane == 0) {
        int i = warp & (NN - 1);
        float dg = row[i];
        float rs = s - dg + 1.0f;          // replace diag by 1
        g_deg[warp]  = rsqrtf(fmaxf(rs, 1.0f));
        g_diag[warp] = dg;
    }
}

// ---------------- kernel B: H' = diag(d) * (x @ [Wq|Wk|Wv]) ------------------
__global__ void __launch_bounds__(320) h_kernel(const float* __restrict__ x,
                                                const float* __restrict__ Wq,
                                                const float* __restrict__ Wk,
                                                const float* __restrict__ Wv) {
    __shared__ float xs[64][IND];
    int b = blockIdx.y;
    int rb = blockIdx.x;
    int t = threadIdx.x;
    size_t rowbase = ((size_t)b * NN + rb * 64);

    for (int idx = t; idx < 64 * IND; idx += 320) {
        int r = idx >> 6, k = idx & 63;
        xs[r][k] = x[(rowbase + r) * IND + k];
    }
    __syncthreads();

    const float* Wcol;
    int stride;
    if (t < 128)      { Wcol = Wq + t;          stride = 128; }
    else if (t < 256) { Wcol = Wk + (t - 128);  stride = 128; }
    else              { Wcol = Wv + (t - 256);  stride = 64;  }

    float w[64];
#pragma unroll
    for (int k = 0; k < 64; k++) w[k] = Wcol[(size_t)k * stride];

    const float4* xs4 = (const float4*)&xs[0][0];
    for (int r = 0; r < 64; r++) {
        float acc = 0.f;
#pragma unroll
        for (int kq = 0; kq < 16; kq++) {
            float4 xv = xs4[r * 16 + kq];
            acc += xv.x * w[kq * 4 + 0];
            acc += xv.y * w[kq * 4 + 1];
            acc += xv.z * w[kq * 4 + 2];
            acc += xv.w * w[kq * 4 + 3];
        }
        g_H[(rowbase + r) * CTOT + t] = g_deg[rowbase + r] * acc;
    }
}

// ---------------- kernel C: tf32 tensor-core GCN GEMM -----------------------
// C = diag(d) * (adj_raw @ H' + (1-diag)*H'_row) + bias, routed to Q/K/V.
// CTA tile 128(M) x 64(N), K step 32. 8 warps in 4(m) x 2(n); warp = 32x32.
#define ASTRIDE 36   // (4r+c)%32 distinct per warp-frag -> conflict-free
#define BSTRIDE 72   // (8k+n)%32 distinct per warp-frag -> conflict-free

__global__ void __launch_bounds__(256) gcn_gemm_tc(const float* __restrict__ adj,
                                                   const float* __restrict__ bq,
                                                   const float* __restrict__ bk,
                                                   const float* __restrict__ bv,
                                                   float* __restrict__ outV) {
    __shared__ float As[128 * ASTRIDE];   // 18432 B
    __shared__ float Bs[32 * BSTRIDE];    //  9216 B

    int b  = blockIdx.z;
    int mt = blockIdx.y;     // 0..7 -> 128-row tiles
    int cb = blockIdx.x;     // 0..4 -> 64-col tiles of 320
    int t  = threadIdx.x;
    int wid = t >> 5, lane = t & 31;
    int g = lane >> 2, tg = lane & 3;
    int wm = wid >> 1, wn = wid & 1;

    const float* adjb = adj + (size_t)b * NN * NN + (size_t)(mt * 128) * NN;
    const float* Hb   = g_H + (size_t)b * NN * CTOT;
    int colbase = cb * 64;

    float acc[2][4][4];
#pragma unroll
    for (int m = 0; m < 2; m++)
#pragma unroll
        for (int n = 0; n < 4; n++)
#pragma unroll
            for (int e = 0; e < 4; e++) acc[m][n][e] = 0.f;

    for (int k0 = 0; k0 < NN; k0 += 32) {
        // A tile: 128 rows x 32 k
#pragma unroll
        for (int i = 0; i < 4; i++) {
            int lin = t + i * 256;          // 0..1023
            int r = lin >> 3, q = lin & 7;
            float4 v = *(const float4*)(adjb + (size_t)r * NN + k0 + q * 4);
            *(float4*)&As[r * ASTRIDE + q * 4] = v;
        }
        // B tile: 32 k x 64 cols
#pragma unroll
        for (int i = 0; i < 2; i++) {
            int lin = t + i * 256;          // 0..511
            int kk = lin >> 4, q = lin & 15;
            float4 v = *(const float4*)(Hb + (size_t)(k0 + kk) * CTOT + colbase + q * 4);
            *(float4*)&Bs[kk * BSTRIDE + q * 4] = v;
        }
        __syncthreads();

#pragma unroll
        for (int ks = 0; ks < 4; ks++) {
            int kb = ks * 8;
            uint32_t a[2][4];
#pragma unroll
            for (int m = 0; m < 2; m++) {
                int rb = wm * 32 + m * 16;
                a[m][0] = f2tf32(As[(rb + g)     * ASTRIDE + kb + tg]);
                a[m][1] = f2tf32(As[(rb + g + 8) * ASTRIDE + kb + tg]);
                a[m][2] = f2tf32(As[(rb + g)     * ASTRIDE + kb + tg + 4]);
                a[m][3] = f2tf32(As[(rb + g + 8) * ASTRIDE + kb + tg + 4]);
            }
#pragma unroll
            for (int n = 0; n < 4; n++) {
                int cc = wn * 32 + n * 8 + g;
                uint32_t b0 = f2tf32(Bs[(kb + tg)     * BSTRIDE + cc]);
                uint32_t b1 = f2tf32(Bs[(kb + tg + 4) * BSTRIDE + cc]);
#pragma unroll
                for (int m = 0; m < 2; m++)
                    mma_tf32(acc[m][n], a[m][0], a[m][1], a[m][2], a[m][3], b0, b1);
            }
        }
        __syncthreads();
    }

    // epilogue: route to g_Q / g_K / outV (each 64-col tile hits one dest)
    float* dst; const float* barr; int jb, stride;
    if (cb < 2)      { dst = g_Q + (size_t)b * NN * ATTN;  barr = bq; jb = cb * 64;       stride = ATTN; }
    else if (cb < 4) { dst = g_K + (size_t)b * NN * ATTN;  barr = bk; jb = (cb - 2) * 64; stride = ATTN; }
    else             { dst = outV + (size_t)b * NN * OUTD; barr = bv; jb = 0;             stride = OUTD; }

#pragma unroll
    for (int m = 0; m < 2; m++) {
        int r0 = mt * 128 + wm * 32 + m * 16 + g;
#pragma unroll
        for (int rr = 0; rr < 2; rr++) {
            int i = r0 + rr * 8;
            size_t gi = (size_t)b * NN + i;
            float d    = g_deg[gi];
            float corr = 1.0f - g_diag[gi];
#pragma unroll
            for (int n = 0; n < 4; n++) {
                int jl = jb + wn * 32 + n * 8 + 2 * tg;         // local col in dest
                int jg = colbase + wn * 32 + n * 8 + 2 * tg;    // global col 0..319
                float2 h2 = *(const float2*)(Hb + (size_t)i * CTOT + jg);
                float v0 = d * (acc[m][n][rr * 2 + 0] + corr * h2.x) + barr[jl];
                float v1 = d * (acc[m][n][rr * 2 + 1] + corr * h2.y) + barr[jl + 1];
                float2 ov; ov.x = v0; ov.y = v1;
                *(float2*)(dst + (size_t)i * stride + jl) = ov;
            }
        }
    }
}

// ---------------- kernel D: tensor-core A = sym(mean_h tanh(Qh Khᵀ / 8)) ----
#define QS 132                 // padded Q/K tile row: (4r+c)%32 conflict-free
#define TS 65                  // padded 64x64 tile row

__device__ __forceinline__ void load_tile64(float* dst, const float* src,
                                            int b, int tile, int t) {
    const float* p = src + ((size_t)b * NN + tile * 64) * ATTN;
    for (int idx = t; idx < 64 * 32; idx += 256) {   // float4 units
        int r = idx >> 5, q = idx & 31;
        float4 v = *(const float4*)(p + r * ATTN + q * 4);
        *(float4*)(dst + r * QS + q * 4) = v;
    }
}

// warp layout: 8 warps = 4(m) x 2(n); warp = 16 rows x 32 cols (4 n-frags).
__device__ __forceinline__ void attn_compute(const float* __restrict__ Qs,
                                             const float* __restrict__ Ks,
                                             int wm, int wn, int g, int tg,
                                             float out[4][4]) {
#pragma unroll
    for (int n = 0; n < 4; n++)
#pragma unroll
        for (int e = 0; e < 4; e++) out[n][e] = 0.f;

#pragma unroll
    for (int h = 0; h < 4; h++) {
        float acc[4][4];
#pragma unroll
        for (int n = 0; n < 4; n++)
#pragma unroll
            for (int e = 0; e < 4; e++) acc[n][e] = 0.f;

#pragma unroll
        for (int ks = 0; ks < 4; ks++) {
            int kb = h * 32 + ks * 8;
            int rb = wm * 16;
            uint32_t a0 = f2tf32(Qs[(rb + g)     * QS + kb + tg]);
            uint32_t a1 = f2tf32(Qs[(rb + g + 8) * QS + kb + tg]);
            uint32_t a2 = f2tf32(Qs[(rb + g)     * QS + kb + tg + 4]);
            uint32_t a3 = f2tf32(Qs[(rb + g + 8) * QS + kb + tg + 4]);
#pragma unroll
            for (int n = 0; n < 4; n++) {
                int cc = wn * 32 + n * 8 + g;
                uint32_t b0 = f2tf32(Ks[cc * QS + kb + tg]);
                uint32_t b1 = f2tf32(Ks[cc * QS + kb + tg + 4]);
                mma_tf32(acc[n], a0, a1, a2, a3, b0, b1);
            }
        }
#pragma unroll
        for (int n = 0; n < 4; n++)
#pragma unroll
            for (int e = 0; e < 4; e++)
                out[n][e] += tanhf(acc[n][e] * 0.125f);   // / sqrt(64)
    }
#pragma unroll
    for (int n = 0; n < 4; n++)
#pragma unroll
        for (int e = 0; e < 4; e++) out[n][e] *= 0.25f;   // head mean
}

#define SMEM_D ((2 * 64 * QS + 2 * 64 * TS) * (int)sizeof(float))  // 100864 B

__global__ void __launch_bounds__(256) attn_tc(float* __restrict__ outA) {
    extern __shared__ float sm[];
    float* Qs = sm;
    float* Ks = sm + 64 * QS;
    float* T1 = sm + 2 * 64 * QS;
    float* C2 = T1 + 64 * TS;

    int I = blockIdx.x, J = blockIdx.y, b = blockIdx.z;
    if (J < I) return;
    int t = threadIdx.x;
    int wid = t >> 5, lane = t & 31;
    int g = lane >> 2, tg = lane & 3;
    int wm = wid >> 1, wn = wid & 1;

    load_tile64(Qs, g_Q, b, I, t);
    load_tile64(Ks, g_K, b, J, t);
    __syncthreads();

    float o1[4][4];
    attn_compute(Qs, Ks, wm, wn, g, tg, o1);   // raw tile (I,J)
#pragma unroll
    for (int n = 0; n < 4; n++)
#pragma unroll
        for (int e = 0; e < 4; e++) {
            int r = wm * 16 + g + (e >> 1) * 8;
            int c = wn * 32 + n * 8 + 2 * tg + (e & 1);
            T1[r * TS + c] = o1[n][e];
        }
    __syncthreads();

    if (I == J) {
        for (int idx = t; idx < 4096; idx += 256) {
            int r = idx >> 6, c = idx & 63;
            C2[r * TS + c] = 0.5f * (T1[r * TS + c] + T1[c * TS + r]);
        }
        __syncthreads();
    } else {
        load_tile64(Qs, g_Q, b, J, t);
        load_tile64(Ks, g_K, b, I, t);
        __syncthreads();
        float o2[4][4];
        attn_compute(Qs, Ks, wm, wn, g, tg, o2);  // raw tile (J,I)
        // C2[r][c] = 0.5*(raw(J,I)[r][c] + raw(I,J)[c][r])
#pragma unroll
        for (int n = 0; n < 4; n++)
#pragma unroll
            for (int e = 0; e < 4; e++) {
                int r = wm * 16 + g + (e >> 1) * 8;
                int c = wn * 32 + n * 8 + 2 * tg + (e & 1);
                C2[r * TS + c] = 0.5f * (o2[n][e] + T1[c * TS + r]);
            }
        __syncthreads();
    }

    // C2 holds output tile (J,I); write it, and its transpose to (I,J).
    float* ob = outA + ((size_t)b * NN + J * 64) * NN + I * 64;
    for (int idx = t; idx < 4096; idx += 256) {
        int r = idx >> 6, c = idx & 63;
        ob[(size_t)r * NN + c] = C2[r * TS + c];
    }
    if (I != J) {
        float* ob2 = outA + ((size_t)b * NN + I * 64) * NN + J * 64;
        for (int idx = t; idx < 4096; idx += 256) {
            int r = idx >> 6, c = idx & 63;
            ob2[(size_t)r * NN + c] = C2[c * TS + r];
        }
    }
}

// ---------------- launch -----------------------------------------------------
extern "C" void kernel_launch(void* const* d_in, const int* in_sizes, int n_in,
                              void* d_out, int out_size) {
    (void)in_sizes; (void)n_in; (void)out_size;
    const float* x   = (const float*)d_in[0];
    const float* adj = (const float*)d_in[1];
    // d_in[2] = flags (unused by reference)
    const float* Wq = (const float*)d_in[3];
    const float* bq = (const float*)d_in[4];
    const float* Wk = (const float*)d_in[5];
    const float* bk = (const float*)d_in[6];
    const float* Wv = (const float*)d_in[7];
    const float* bv = (const float*)d_in[8];

    float* outV = (float*)d_out;                            // [B,N,64]
    float* outA = (float*)d_out + (size_t)BB * NN * OUTD;   // [B,N,N]

    cudaFuncSetAttribute(attn_tc,
                         cudaFuncAttributeMaxDynamicSharedMemorySize, SMEM_D);

    deg_kernel<<<(BB * NN) / 8, 256>>>(adj);
    h_kernel<<<dim3(16, BB), 320>>>(x, Wq, Wk, Wv);
    gcn_gemm_tc<<<dim3(5, 8, BB), 256>>>(adj, bq, bk, bv, outV);
    attn_tc<<<dim3(16, 16, BB), 256, SMEM_D>>>(outA);
}

// round 3
// speedup vs baseline: 2.5989x; 1.0834x over previous
#include <cuda_runtime.h>
#include <math.h>
#include <cstdint>

#define BB 32
#define NN 1024
#define IND 64
#define ATTN 128
#define OUTD 64
#define CTOT 320   // Q(128) | K(128) | V(64)

// ---------------- scratch (device globals; no allocations allowed) ----------
__device__ float g_deg[BB * NN];
__device__ float g_diag[BB * NN];
__device__ float g_H[(size_t)BB * NN * CTOT];   // d-prescaled x@W, tf32-rounded
__device__ float g_Q[(size_t)BB * NN * ATTN];   // tf32-rounded
__device__ float g_K[(size_t)BB * NN * ATTN];   // tf32-rounded

// ---------------- tf32 MMA helpers -----------------------------------------
__device__ __forceinline__ uint32_t f2tf32(float x) {
    uint32_t r;
    asm("cvt.rna.tf32.f32 %0, %1;" : "=r"(r) : "f"(x));
    return r;
}
__device__ __forceinline__ float f2tf32f(float x) {
    return __uint_as_float(f2tf32(x));
}

__device__ __forceinline__ void mma_tf32(float c[4],
                                         uint32_t a0, uint32_t a1, uint32_t a2, uint32_t a3,
                                         uint32_t b0, uint32_t b1) {
    asm volatile(
        "mma.sync.aligned.m16n8k8.row.col.f32.tf32.tf32.f32 "
        "{%0,%1,%2,%3}, {%4,%5,%6,%7}, {%8,%9}, {%0,%1,%2,%3};\n"
        : "+f"(c[0]), "+f"(c[1]), "+f"(c[2]), "+f"(c[3])
        : "r"(a0), "r"(a1), "r"(a2), "r"(a3), "r"(b0), "r"(b1));
}

// fast accurate tanh: (e^{2x}-1)/(e^{2x}+1) via MUFU; ~1e-6 rel err
__device__ __forceinline__ float fast_tanh(float x) {
    float a = fminf(x * 2.885390082f, 126.0f);   // 2*log2(e); clamp vs overflow
    float e;
    asm("ex2.approx.f32 %0, %1;" : "=f"(e) : "f"(a));
    float r;
    asm("rcp.approx.f32 %0, %1;" : "=f"(r) : "f"(e + 1.0f));
    return (e - 1.0f) * r;
}

// ---------------- kernel A: row degrees + diagonal --------------------------
__global__ void __launch_bounds__(256) deg_kernel(const float* __restrict__ adj) {
    int warp = (blockIdx.x * blockDim.x + threadIdx.x) >> 5;
    int lane = threadIdx.x & 31;
    if (warp >= BB * NN) return;
    const float* row = adj + (size_t)warp * NN;
    const float4* r4 = (const float4*)row;
    float s = 0.f;
#pragma unroll
    for (int j = lane; j < NN / 4; j += 32) {
        float4 v = r4[j];
        s += (v.x + v.y) + (v.z + v.w);
    }
#pragma unroll
    for (int o = 16; o; o >>= 1) s += __shfl_xor_sync(0xffffffffu, s, o);
    if (lane == 0) {
        int i = warp & (NN - 1);
        float dg = row[i];
        float rs = s - dg + 1.0f;          // replace diag by 1
        g_deg[warp]  = rsqrtf(fmaxf(rs, 1.0f));
        g_diag[warp] = dg;
    }
}

// ---------------- kernel B: H' = tf32(diag(d) * (x @ [Wq|Wk|Wv])) ------------
__global__ void __launch_bounds__(320) h_kernel(const float* __restrict__ x,
                                                const float* __restrict__ Wq,
                                                const float* __restrict__ Wk,
                                                const float* __restrict__ Wv) {
    __shared__ float xs[64][IND];
    int b = blockIdx.y;
    int rb = blockIdx.x;
    int t = threadIdx.x;
    size_t rowbase = ((size_t)b * NN + rb * 64);

    for (int idx = t; idx < 64 * IND; idx += 320) {
        int r = idx >> 6, k = idx & 63;
        xs[r][k] = x[(rowbase + r) * IND + k];
    }
    __syncthreads();

    const float* Wcol;
    int stride;
    if (t < 128)      { Wcol = Wq + t;          stride = 128; }
    else if (t < 256) { Wcol = Wk + (t - 128);  stride = 128; }
    else              { Wcol = Wv + (t - 256);  stride = 64;  }

    float w[64];
#pragma unroll
    for (int k = 0; k < 64; k++) w[k] = Wcol[(size_t)k * stride];

    const float4* xs4 = (const float4*)&xs[0][0];
    for (int r = 0; r < 64; r++) {
        float acc = 0.f;
#pragma unroll
        for (int kq = 0; kq < 16; kq++) {
            float4 xv = xs4[r * 16 + kq];
            acc += xv.x * w[kq * 4 + 0];
            acc += xv.y * w[kq * 4 + 1];
            acc += xv.z * w[kq * 4 + 2];
            acc += xv.w * w[kq * 4 + 3];
        }
        g_H[(rowbase + r) * CTOT + t] = f2tf32f(g_deg[rowbase + r] * acc);
    }
}

// ---------------- kernel C: tf32 tensor-core GCN GEMM -----------------------
// C = diag(d) * (adj_raw @ H' + (1-diag)*H'_row) + bias, routed to Q/K/V.
// CTA tile 128(M) x 64(N), K step 32. 8 warps in 4(m) x 2(n); warp = 32x32.
// Register-prefetch double buffering; operands pre-rounded to tf32 at staging.
#define ASTRIDE 36
#define BSTRIDE 72

__global__ void __launch_bounds__(256) gcn_gemm_tc(const float* __restrict__ adj,
                                                   const float* __restrict__ bq,
                                                   const float* __restrict__ bk,
                                                   const float* __restrict__ bv,
                                                   float* __restrict__ outV) {
    __shared__ float As[128 * ASTRIDE];   // 18432 B
    __shared__ float Bs[32 * BSTRIDE];    //  9216 B

    int b  = blockIdx.z;
    int mt = blockIdx.y;     // 0..7 -> 128-row tiles
    int cb = blockIdx.x;     // 0..4 -> 64-col tiles of 320
    int t  = threadIdx.x;
    int wid = t >> 5, lane = t & 31;
    int g = lane >> 2, tg = lane & 3;
    int wm = wid >> 1, wn = wid & 1;

    const float* adjb = adj + (size_t)b * NN * NN + (size_t)(mt * 128) * NN;
    const float* Hb   = g_H + (size_t)b * NN * CTOT;
    int colbase = cb * 64;

    // staging indices (fixed per thread)
    int ar[4], aq[4];
#pragma unroll
    for (int i = 0; i < 4; i++) { int lin = t + i * 256; ar[i] = lin >> 3; aq[i] = lin & 7; }
    int bk_[2], bq_[2];
#pragma unroll
    for (int i = 0; i < 2; i++) { int lin = t + i * 256; bk_[i] = lin >> 4; bq_[i] = lin & 15; }

    float4 pa[4], pb[2];
#define LOAD_PREF(K0)                                                              \
    {                                                                              \
        _Pragma("unroll")                                                          \
        for (int i = 0; i < 4; i++)                                                \
            pa[i] = *(const float4*)(adjb + (size_t)ar[i] * NN + (K0) + aq[i] * 4);\
        _Pragma("unroll")                                                          \
        for (int i = 0; i < 2; i++)                                                \
            pb[i] = *(const float4*)(Hb + (size_t)((K0) + bk_[i]) * CTOT + colbase + bq_[i] * 4); \
    }
#define STORE_SMEM()                                                               \
    {                                                                              \
        _Pragma("unroll")                                                          \
        for (int i = 0; i < 4; i++) {                                              \
            float4 v = pa[i];                                                      \
            v.x = f2tf32f(v.x); v.y = f2tf32f(v.y);                                \
            v.z = f2tf32f(v.z); v.w = f2tf32f(v.w);                                \
            *(float4*)&As[ar[i] * ASTRIDE + aq[i] * 4] = v;                        \
        }                                                                          \
        _Pragma("unroll")                                                          \
        for (int i = 0; i < 2; i++)                                                \
            *(float4*)&Bs[bk_[i] * BSTRIDE + bq_[i] * 4] = pb[i];                  \
    }

    float acc[2][4][4];
#pragma unroll
    for (int m = 0; m < 2; m++)
#pragma unroll
        for (int n = 0; n < 4; n++)
#pragma unroll
            for (int e = 0; e < 4; e++) acc[m][n][e] = 0.f;

    LOAD_PREF(0);
    STORE_SMEM();

    for (int k0 = 0; k0 < NN; k0 += 32) {
        __syncthreads();
        if (k0 + 32 < NN) LOAD_PREF(k0 + 32);

#pragma unroll
        for (int ks = 0; ks < 4; ks++) {
            int kb = ks * 8;
            uint32_t a[2][4];
#pragma unroll
            for (int m = 0; m < 2; m++) {
                int rb = wm * 32 + m * 16;
                a[m][0] = __float_as_uint(As[(rb + g)     * ASTRIDE + kb + tg]);
                a[m][1] = __float_as_uint(As[(rb + g + 8) * ASTRIDE + kb + tg]);
                a[m][2] = __float_as_uint(As[(rb + g)     * ASTRIDE + kb + tg + 4]);
                a[m][3] = __float_as_uint(As[(rb + g + 8) * ASTRIDE + kb + tg + 4]);
            }
#pragma unroll
            for (int n = 0; n < 4; n++) {
                int cc = wn * 32 + n * 8 + g;
                uint32_t b0 = __float_as_uint(Bs[(kb + tg)     * BSTRIDE + cc]);
                uint32_t b1 = __float_as_uint(Bs[(kb + tg + 4) * BSTRIDE + cc]);
#pragma unroll
                for (int m = 0; m < 2; m++)
                    mma_tf32(acc[m][n], a[m][0], a[m][1], a[m][2], a[m][3], b0, b1);
            }
        }
        __syncthreads();
        if (k0 + 32 < NN) STORE_SMEM();
    }

    // epilogue: route to g_Q / g_K / outV; round Q/K to tf32 for the attn pass
    float* dst; const float* barr; int jb, stride; bool roundout;
    if (cb < 2)      { dst = g_Q + (size_t)b * NN * ATTN;  barr = bq; jb = cb * 64;       stride = ATTN; roundout = true; }
    else if (cb < 4) { dst = g_K + (size_t)b * NN * ATTN;  barr = bk; jb = (cb - 2) * 64; stride = ATTN; roundout = true; }
    else             { dst = outV + (size_t)b * NN * OUTD; barr = bv; jb = 0;             stride = OUTD; roundout = false; }

#pragma unroll
    for (int m = 0; m < 2; m++) {
        int r0 = mt * 128 + wm * 32 + m * 16 + g;
#pragma unroll
        for (int rr = 0; rr < 2; rr++) {
            int i = r0 + rr * 8;
            size_t gi = (size_t)b * NN + i;
            float d    = g_deg[gi];
            float corr = 1.0f - g_diag[gi];
#pragma unroll
            for (int n = 0; n < 4; n++) {
                int jl = jb + wn * 32 + n * 8 + 2 * tg;
                int jg = colbase + wn * 32 + n * 8 + 2 * tg;
                float2 h2 = *(const float2*)(Hb + (size_t)i * CTOT + jg);
                float v0 = d * (acc[m][n][rr * 2 + 0] + corr * h2.x) + barr[jl];
                float v1 = d * (acc[m][n][rr * 2 + 1] + corr * h2.y) + barr[jl + 1];
                if (roundout) { v0 = f2tf32f(v0); v1 = f2tf32f(v1); }
                float2 ov; ov.x = v0; ov.y = v1;
                *(float2*)(dst + (size_t)i * stride + jl) = ov;
            }
        }
    }
}

// ---------------- kernel D: tensor-core A = sym(mean_h tanh(Qh Khᵀ / 8)) ----
#define QS 132
#define TS 65

__device__ __forceinline__ void load_tile64(float* dst, const float* src,
                                            int b, int tile, int t) {
    const float* p = src + ((size_t)b * NN + tile * 64) * ATTN;
    for (int idx = t; idx < 64 * 32; idx += 256) {
        int r = idx >> 5, q = idx & 31;
        float4 v = *(const float4*)(p + r * ATTN + q * 4);
        *(float4*)(dst + r * QS + q * 4) = v;
    }
}

// warp layout: 8 warps = 4(m) x 2(n); warp = 16 rows x 32 cols.
// Operands already tf32-rounded: no cvt in the hot loop.
__device__ __forceinline__ void attn_compute(const float* __restrict__ Qs,
                                             const float* __restrict__ Ks,
                                             int wm, int wn, int g, int tg,
                                             float out[4][4]) {
#pragma unroll
    for (int n = 0; n < 4; n++)
#pragma unroll
        for (int e = 0; e < 4; e++) out[n][e] = 0.f;

#pragma unroll
    for (int h = 0; h < 4; h++) {
        float acc[4][4];
#pragma unroll
        for (int n = 0; n < 4; n++)
#pragma unroll
            for (int e = 0; e < 4; e++) acc[n][e] = 0.f;

#pragma unroll
        for (int ks = 0; ks < 4; ks++) {
            int kb = h * 32 + ks * 8;
            int rb = wm * 16;
            uint32_t a0 = __float_as_uint(Qs[(rb + g)     * QS + kb + tg]);
            uint32_t a1 = __float_as_uint(Qs[(rb + g + 8) * QS + kb + tg]);
            uint32_t a2 = __float_as_uint(Qs[(rb + g)     * QS + kb + tg + 4]);
            uint32_t a3 = __float_as_uint(Qs[(rb + g + 8) * QS + kb + tg + 4]);
#pragma unroll
            for (int n = 0; n < 4; n++) {
                int cc = wn * 32 + n * 8 + g;
                uint32_t b0 = __float_as_uint(Ks[cc * QS + kb + tg]);
                uint32_t b1 = __float_as_uint(Ks[cc * QS + kb + tg + 4]);
                mma_tf32(acc[n], a0, a1, a2, a3, b0, b1);
            }
        }
#pragma unroll
        for (int n = 0; n < 4; n++)
#pragma unroll
            for (int e = 0; e < 4; e++)
                out[n][e] += fast_tanh(acc[n][e] * 0.125f);   // / sqrt(64)
    }
#pragma unroll
    for (int n = 0; n < 4; n++)
#pragma unroll
        for (int e = 0; e < 4; e++) out[n][e] *= 0.25f;       // head mean
}

#define SMEM_D ((2 * 64 * QS + 2 * 64 * TS) * (int)sizeof(float))  // 100864 B

__global__ void __launch_bounds__(256) attn_tc(float* __restrict__ outA) {
    extern __shared__ float sm[];
    float* Qs = sm;
    float* Ks = sm + 64 * QS;
    float* T1 = sm + 2 * 64 * QS;
    float* C2 = T1 + 64 * TS;

    int I = blockIdx.x, J = blockIdx.y, b = blockIdx.z;
    if (J < I) return;
    int t = threadIdx.x;
    int wid = t >> 5, lane = t & 31;
    int g = lane >> 2, tg = lane & 3;
    int wm = wid >> 1, wn = wid & 1;

    load_tile64(Qs, g_Q, b, I, t);
    load_tile64(Ks, g_K, b, J, t);
    __syncthreads();

    float o1[4][4];
    attn_compute(Qs, Ks, wm, wn, g, tg, o1);   // raw tile (I,J)
#pragma unroll
    for (int n = 0; n < 4; n++)
#pragma unroll
        for (int e = 0; e < 4; e++) {
            int r = wm * 16 + g + (e >> 1) * 8;
            int c = wn * 32 + n * 8 + 2 * tg + (e & 1);
            T1[r * TS + c] = o1[n][e];
        }
    __syncthreads();

    if (I == J) {
        for (int idx = t; idx < 4096; idx += 256) {
            int r = idx >> 6, c = idx & 63;
            C2[r * TS + c] = 0.5f * (T1[r * TS + c] + T1[c * TS + r]);
        }
        __syncthreads();
    } else {
        load_tile64(Qs, g_Q, b, J, t);
        load_tile64(Ks, g_K, b, I, t);
        __syncthreads();
        float o2[4][4];
        attn_compute(Qs, Ks, wm, wn, g, tg, o2);  // raw tile (J,I)
#pragma unroll
        for (int n = 0; n < 4; n++)
#pragma unroll
            for (int e = 0; e < 4; e++) {
                int r = wm * 16 + g + (e >> 1) * 8;
                int c = wn * 32 + n * 8 + 2 * tg + (e & 1);
                C2[r * TS + c] = 0.5f * (o2[n][e] + T1[c * TS + r]);
            }
        __syncthreads();
    }

    // C2 holds output tile (J,I); write it, and its transpose to (I,J).
    float* ob = outA + ((size_t)b * NN + J * 64) * NN + I * 64;
    for (int idx = t; idx < 4096; idx += 256) {
        int r = idx >> 6, c = idx & 63;
        ob[(size_t)r * NN + c] = C2[r * TS + c];
    }
    if (I != J) {
        float* ob2 = outA + ((size_t)b * NN + I * 64) * NN + J * 64;
        for (int idx = t; idx < 4096; idx += 256) {
            int r = idx >> 6, c = idx & 63;
            ob2[(size_t)r * NN + c] = C2[c * TS + r];
        }
    }
}

// ---------------- launch -----------------------------------------------------
extern "C" void kernel_launch(void* const* d_in, const int* in_sizes, int n_in,
                              void* d_out, int out_size) {
    (void)in_sizes; (void)n_in; (void)out_size;
    const float* x   = (const float*)d_in[0];
    const float* adj = (const float*)d_in[1];
    // d_in[2] = flags (unused by reference)
    const float* Wq = (const float*)d_in[3];
    const float* bq = (const float*)d_in[4];
    const float* Wk = (const float*)d_in[5];
    const float* bk = (const float*)d_in[6];
    const float* Wv = (const float*)d_in[7];
    const float* bv = (const float*)d_in[8];

    float* outV = (float*)d_out;                            // [B,N,64]
    float* outA = (float*)d_out + (size_t)BB * NN * OUTD;   // [B,N,N]

    cudaFuncSetAttribute(attn_tc,
                         cudaFuncAttributeMaxDynamicSharedMemorySize, SMEM_D);

    deg_kernel<<<(BB * NN) / 8, 256>>>(adj);
    h_kernel<<<dim3(16, BB), 320>>>(x, Wq, Wk, Wv);
    gcn_gemm_tc<<<dim3(5, 8, BB), 256>>>(adj, bq, bk, bv, outV);
    attn_tc<<<dim3(16, 16, BB), 256, SMEM_D>>>(outA);
}